// round 12
// baseline (speedup 1.0000x reference)
#include <cuda_runtime.h>
#include <math_constants.h>

// Prefix-max (cumulative max) along H for x of shape (B=32, C=1, H=1024, W=1024), fp32.
// Layout: x[(b*H + h)*W + w]. 32768 independent columns (b,w), scan length H=1024.
//
// Combines the three individually-best measured settings:
//   (a) 128B warp-lines: 32-column tiles, warp = 32 lanes over 32 consecutive
//       columns -> every LDG/STG is one fully-used 128B line (best ncu time, R6).
//   (b) 8 CTAs/SM: 256 threads, <=32 regs (__launch_bounds__(256, 8)).
//   (c) SINGLE-WAVE grid: 1024 CTAs < 148*8 = 1184 concurrent -> whole grid
//       co-resident, no wave quantization, no tail (fixes R6's scored regression).
// Per CTA: 32 cols x full H as 16 passes of 8 chunks x 8 rows/thread.
// Per pass: coalesced full-line loads, local prefix-max, chunk totals -> smem
// (1 barrier), warp scans 4 columns via width-8 shuffles (3 rounds, no
// barrier), read-back (1 barrier), apply carry, coalesced full-line stores.
// Double-buffered smem: 2 barriers per pass.

#define H_DIM 1024
#define W_DIM 1024
#define COLS_PER_BLOCK 32
#define CHUNKS 8
#define ROWS_PER_THREAD 8     // per pass
#define PASS_ROWS 64          // CHUNKS * ROWS_PER_THREAD
#define NUM_PASSES 16

__global__ __launch_bounds__(256, 8)
void cummax_kernel(const float* __restrict__ x, float* __restrict__ out) {
    const int tid   = threadIdx.x;
    const int c     = tid & (COLS_PER_BLOCK - 1);   // 0..31
    const int chunk = tid >> 5;                     // 0..7 (== warp id)
    const int wid   = tid >> 5;
    const int lane  = tid & 31;

    const int col = blockIdx.x * COLS_PER_BLOCK + c;  // 1024 % 32 == 0: no b straddle
    const int b   = col >> 10;
    const int w   = col & (W_DIM - 1);

    const int base0 = b * (H_DIM * W_DIM) + w + chunk * ROWS_PER_THREAD * W_DIM;

    __shared__ float s[2][CHUNKS][COLS_PER_BLOCK + 1];   // double buffer, padded

    // Scan mapping: warp `wid` scans columns 4*wid .. 4*wid+3;
    // lane = scan_col_sub * 8 + scan_ch  (width-8 shuffle groups).
    const int scan_col = 4 * wid + (lane >> 3);
    const int scan_ch  = lane & 7;

    float carry = -CUDART_INF_F;

#pragma unroll
    for (int p = 0; p < NUM_PASSES; p++) {
        const int buf  = p & 1;
        const int base = base0 + p * PASS_ROWS * W_DIM;
        const float* __restrict__ src = x   + base;
        float*       __restrict__ dst = out + base;

        // Load 8 rows: each warp-load is one contiguous, fully-used 128B line.
        float v[ROWS_PER_THREAD];
#pragma unroll
        for (int i = 0; i < ROWS_PER_THREAD; i++) {
            v[i] = src[i * W_DIM];
        }
#pragma unroll
        for (int i = 1; i < ROWS_PER_THREAD; i++) {
            v[i] = fmaxf(v[i], v[i - 1]);
        }

        // Cross-chunk inclusive max-scan of totals via width-8 warp shuffles.
        s[buf][chunk][c] = v[ROWS_PER_THREAD - 1];
        __syncthreads();

        {
            float t = s[buf][scan_ch][scan_col];
#pragma unroll
            for (int d = 1; d < 8; d <<= 1) {
                float o = __shfl_up_sync(0xFFFFFFFFu, t, d, 8);
                if (scan_ch >= d) t = fmaxf(t, o);
            }
            s[buf][scan_ch][scan_col] = t;
        }
        __syncthreads();

        // Exclusive carry: preceding chunks of this pass + previous passes.
        const float excl = (chunk > 0) ? s[buf][chunk - 1][c] : -CUDART_INF_F;
        const float m = fmaxf(carry, excl);

#pragma unroll
        for (int i = 0; i < ROWS_PER_THREAD; i++) {
            dst[i * W_DIM] = fmaxf(v[i], m);
        }

        carry = fmaxf(carry, s[buf][CHUNKS - 1][c]);
    }
}

extern "C" void kernel_launch(void* const* d_in, const int* in_sizes, int n_in,
                              void* d_out, int out_size) {
    const float* x = (const float*)d_in[0];
    float* out = (float*)d_out;

    const int total_cols = 32 * W_DIM;                        // 32768
    const int grid = total_cols / COLS_PER_BLOCK;             // 1024 (single wave)
    cummax_kernel<<<grid, 256>>>(x, out);
}

// round 13
// speedup vs baseline: 1.0439x; 1.0439x over previous
#include <cuda_runtime.h>
#include <math_constants.h>

// Prefix-max (cumulative max) along H for x of shape (B=32, C=1, H=1024, W=1024), fp32.
// Layout: x[(b*H + h)*W + w]. 32768 independent columns (b,w), scan length H=1024.
//
// FINAL: best scored variant (R5, 45.088us). 512-thread block owns 16
// consecutive float-columns x full H, processed as TWO halves of 512 rows
// (16 rows/thread each, v[16] -> 40 regs -> 3 CTAs/SM via
// __launch_bounds__(512,3)). Grid 2048 -> favorable wave shape under the
// harness's natural-clock replay loop (grid-1024 single-wave variants
// scored worse despite faster isolated ncu times).
//   thread t: c = t & 15, chunk = t >> 4 (32 chunks of 16 rows per half).
//   Per half: coalesced loads (64B warp segments), local prefix-max,
//   chunk totals -> smem (1 barrier), warp-per-column shuffle scan
//   (5 shfl rounds, no barrier), read-back (1 barrier),
//   apply carry (incl. cross-half carry), coalesced stores.
// Double-buffered smem: 2 barriers per half, 4 total.

#define H_DIM 1024
#define W_DIM 1024
#define COLS_PER_BLOCK 16
#define CHUNKS 32
#define ROWS_PER_THREAD 16   // per half
#define HALF_ROWS 512        // CHUNKS * ROWS_PER_THREAD

__global__ __launch_bounds__(512, 3)
void cummax_kernel(const float* __restrict__ x, float* __restrict__ out) {
    const int tid   = threadIdx.x;
    const int c     = tid & (COLS_PER_BLOCK - 1);   // 0..15
    const int chunk = tid >> 4;                     // 0..31
    const int wid   = tid >> 5;                     // 0..15
    const int lane  = tid & 31;

    const int col = blockIdx.x * COLS_PER_BLOCK + c;  // 1024 % 16 == 0: no b straddle
    const int b   = col >> 10;
    const int w   = col & (W_DIM - 1);

    const int base0 = b * (H_DIM * W_DIM) + w + chunk * ROWS_PER_THREAD * W_DIM;

    __shared__ float s[2][CHUNKS][COLS_PER_BLOCK + 1];   // double buffer, padded

    float carry = -CUDART_INF_F;

#pragma unroll
    for (int half = 0; half < 2; half++) {
        const int base = base0 + half * HALF_ROWS * W_DIM;
        const float* __restrict__ src = x   + base;
        float*       __restrict__ dst = out + base;

        // Load 16 rows (coalesced: warp covers 2 rows x 64B fully-used segments).
        float v[ROWS_PER_THREAD];
#pragma unroll
        for (int i = 0; i < ROWS_PER_THREAD; i++) {
            v[i] = src[i * W_DIM];
        }
#pragma unroll
        for (int i = 1; i < ROWS_PER_THREAD; i++) {
            v[i] = fmaxf(v[i], v[i - 1]);
        }

        // Cross-chunk inclusive max-scan of totals via warp shuffles.
        s[half][chunk][c] = v[ROWS_PER_THREAD - 1];
        __syncthreads();

        // Warp `wid` scans column `wid`: lane = chunk index. 16 warps, 16 columns.
        {
            float t = s[half][lane][wid];
#pragma unroll
            for (int d = 1; d < 32; d <<= 1) {
                float o = __shfl_up_sync(0xFFFFFFFFu, t, d);
                if (lane >= d) t = fmaxf(t, o);
            }
            s[half][lane][wid] = t;
        }
        __syncthreads();

        // Exclusive carry (preceding chunks of this half + previous halves).
        const float excl = (chunk > 0) ? s[half][chunk - 1][c] : -CUDART_INF_F;
        const float m = fmaxf(carry, excl);

#pragma unroll
        for (int i = 0; i < ROWS_PER_THREAD; i++) {
            dst[i * W_DIM] = fmaxf(v[i], m);
        }

        carry = fmaxf(carry, s[half][CHUNKS - 1][c]);
    }
}

extern "C" void kernel_launch(void* const* d_in, const int* in_sizes, int n_in,
                              void* d_out, int out_size) {
    const float* x = (const float*)d_in[0];
    float* out = (float*)d_out;

    const int total_cols = 32 * W_DIM;                        // 32768
    const int grid = total_cols / COLS_PER_BLOCK;             // 2048
    cummax_kernel<<<grid, 512>>>(x, out);
}